// round 3
// baseline (speedup 1.0000x reference)
#include <cuda_runtime.h>
#include <math.h>

// Problem constants
#define BB    32
#define CIN   64
#define HIN   128
#define WINP  128
#define COUTT 128
#define OHH   126
#define OWW   126

// Tiling
#define TILE_OH 16
#define TILE_OW 32
#define TILE_CO 32
#define CK      8     // cin chunk

// Block: 256 threads.
//   tc   = tid>>6  in [0,4)   -> cout sub-tile of 8 (co0 + tc*8 + 0..7)
//   tp   = tid&63
//   trow = tp>>2   in [0,16)  -> output row within tile
//   tcg  = tp&3    in [0,4)   -> 8-wide column group
// Each thread: acc[8 couts][8 cols] register tile (64 FMAs per weight-octet).

__global__ __launch_bounds__(256, 2)
void conv3x3_fused_kernel(const float* __restrict__ x,
                          const float* __restrict__ w,
                          const float* __restrict__ bias,
                          const float* __restrict__ mult,
                          float* __restrict__ out)
{
    // stride 35 (odd) -> verified conflict-free for the (row, colgroup) access set
    __shared__ float sx[CK][TILE_OH + 2][TILE_OW + 3];
    __shared__ float sw[CK][3][3][TILE_CO];

    const int tid  = threadIdx.x;
    const int tc   = tid >> 6;
    const int tp   = tid & 63;
    const int trow = tp >> 2;
    const int tcg  = tp & 3;

    const int ow_base = blockIdx.x * TILE_OW;
    const int oh_base = blockIdx.y * TILE_OH;
    const int b       = blockIdx.z >> 2;
    const int co0     = (blockIdx.z & 3) * TILE_CO;

    float acc[8][8];
#pragma unroll
    for (int i = 0; i < 8; i++)
#pragma unroll
        for (int j = 0; j < 8; j++) acc[i][j] = 0.f;

    for (int ci0 = 0; ci0 < CIN; ci0 += CK) {
        // ---- load input tile (CK x 18 x 34), zero-padded at image edges ----
        for (int idx = tid; idx < CK * (TILE_OH + 2) * (TILE_OW + 2); idx += 256) {
            int c  = idx % (TILE_OW + 2);
            int t  = idx / (TILE_OW + 2);
            int r  = t % (TILE_OH + 2);
            int ck = t / (TILE_OH + 2);
            int gh = oh_base + r;
            int gw = ow_base + c;
            float v = 0.f;
            if (gh < HIN && gw < WINP)
                v = x[(((size_t)b * CIN + ci0 + ck) * HIN + gh) * WINP + gw];
            sx[ck][r][c] = v;
        }
        // ---- load weights (CK x 3 x 3 x 32 couts) ----
        for (int idx = tid; idx < CK * 9 * TILE_CO; idx += 256) {
            int co = idx & 31;
            int t  = idx >> 5;
            int kk = t % 9;
            int ck = t / 9;
            sw[ck][kk / 3][kk % 3][co] =
                w[((size_t)(co0 + co) * CIN + ci0 + ck) * 9 + kk];
        }
        __syncthreads();

#pragma unroll 2
        for (int ck = 0; ck < CK; ck++) {
#pragma unroll
            for (int ki = 0; ki < 3; ki++) {
                // 10-wide sliding window covers all three kj shifts
                float win[10];
#pragma unroll
                for (int j = 0; j < 10; j++)
                    win[j] = sx[ck][trow + ki][tcg * 8 + j];
#pragma unroll
                for (int kj = 0; kj < 3; kj++) {
                    float4 w0 = *reinterpret_cast<const float4*>(&sw[ck][ki][kj][tc * 8]);
                    float4 w1 = *reinterpret_cast<const float4*>(&sw[ck][ki][kj][tc * 8 + 4]);
                    float wv[8] = {w0.x, w0.y, w0.z, w0.w, w1.x, w1.y, w1.z, w1.w};
#pragma unroll
                    for (int i = 0; i < 8; i++)
#pragma unroll
                        for (int j = 0; j < 8; j++)
                            acc[i][j] = fmaf(wv[i], win[j + kj], acc[i][j]);
                }
            }
        }
        __syncthreads();
    }

    // ---- fused epilogue: bias -> multiplier -> leaky relu -> tanh-GELU ----
    const int   oh = oh_base + trow;
    const float c0 = 0.7978845608028654f;  // sqrt(2/pi)
#pragma unroll
    for (int i = 0; i < 8; i++) {
        const int   co = co0 + tc * 8 + i;
        const float bi = bias[co];
        const float mu = mult[co];
#pragma unroll
        for (int j = 0; j < 8; j++) {
            const int ow = ow_base + tcg * 8 + j;
            float y = (acc[i][j] + bi) * mu;
            y = (y >= 0.f) ? y : 0.01f * y;
            float t = c0 * (y + 0.044715f * y * y * y);
            float g = 0.5f * y * (1.f + tanhf(t));
            if (oh < OHH && ow < OWW)
                out[(((size_t)b * COUTT + co) * OHH + oh) * OWW + ow] = g;
        }
    }
}

extern "C" void kernel_launch(void* const* d_in, const int* in_sizes, int n_in,
                              void* d_out, int out_size)
{
    const float* x    = (const float*)d_in[0];
    const float* w    = (const float*)d_in[1];
    const float* bias = (const float*)d_in[2];
    const float* mult = (const float*)d_in[3];
    float*       out  = (float*)d_out;

    dim3 grid((OWW + TILE_OW - 1) / TILE_OW,   // 4
              (OHH + TILE_OH - 1) / TILE_OH,   // 8
              BB * 4);                         // 32 batches x 4 cout chunks
    conv3x3_fused_kernel<<<grid, 256>>>(x, w, bias, mult, out);
}

// round 4
// speedup vs baseline: 1.0559x; 1.0559x over previous
#include <cuda_runtime.h>
#include <math.h>

// Problem constants
#define BB    32
#define CIN   64
#define HIN   128
#define WINP  128
#define COUTT 128
#define OHH   126
#define OWW   126

// Tiling
#define TILE_OH 16
#define TILE_OW 32
#define TILE_CO 32
#define CK      8     // cin chunk

// Block: 256 threads.
//   tc   = tid>>6  in [0,4)   -> cout sub-tile of 8 (co0 + tc*8 + 0..7)
//   tp   = tid&63
//   trow = tp>>2   in [0,16)  -> output row within tile
//   tcg  = tp&3    in [0,4)   -> 8-wide column group
// Each thread: acc[8 couts][8 cols] register tile (64 FMAs per weight-octet).

__global__ __launch_bounds__(256, 2)
void conv3x3_fused_kernel(const float* __restrict__ x,
                          const float* __restrict__ w,
                          const float* __restrict__ bias,
                          const float* __restrict__ mult,
                          float* __restrict__ out)
{
    // stride 35 (odd) -> verified conflict-free for the (row, colgroup) access set
    __shared__ float sx[CK][TILE_OH + 2][TILE_OW + 3];
    __shared__ float sw[CK][3][3][TILE_CO];

    const int tid  = threadIdx.x;
    const int tc   = tid >> 6;
    const int tp   = tid & 63;
    const int trow = tp >> 2;
    const int tcg  = tp & 3;

    const int ow_base = blockIdx.x * TILE_OW;
    const int oh_base = blockIdx.y * TILE_OH;
    const int b       = blockIdx.z >> 2;
    const int co0     = (blockIdx.z & 3) * TILE_CO;

    float acc[8][8];
#pragma unroll
    for (int i = 0; i < 8; i++)
#pragma unroll
        for (int j = 0; j < 8; j++) acc[i][j] = 0.f;

    for (int ci0 = 0; ci0 < CIN; ci0 += CK) {
        // ---- load input tile (CK x 18 x 34), zero-padded at image edges ----
        for (int idx = tid; idx < CK * (TILE_OH + 2) * (TILE_OW + 2); idx += 256) {
            int c  = idx % (TILE_OW + 2);
            int t  = idx / (TILE_OW + 2);
            int r  = t % (TILE_OH + 2);
            int ck = t / (TILE_OH + 2);
            int gh = oh_base + r;
            int gw = ow_base + c;
            float v = 0.f;
            if (gh < HIN && gw < WINP)
                v = x[(((size_t)b * CIN + ci0 + ck) * HIN + gh) * WINP + gw];
            sx[ck][r][c] = v;
        }
        // ---- load weights (CK x 3 x 3 x 32 couts) ----
        for (int idx = tid; idx < CK * 9 * TILE_CO; idx += 256) {
            int co = idx & 31;
            int t  = idx >> 5;
            int kk = t % 9;
            int ck = t / 9;
            sw[ck][kk / 3][kk % 3][co] =
                w[((size_t)(co0 + co) * CIN + ci0 + ck) * 9 + kk];
        }
        __syncthreads();

#pragma unroll 2
        for (int ck = 0; ck < CK; ck++) {
#pragma unroll
            for (int ki = 0; ki < 3; ki++) {
                // 10-wide sliding window covers all three kj shifts
                float win[10];
#pragma unroll
                for (int j = 0; j < 10; j++)
                    win[j] = sx[ck][trow + ki][tcg * 8 + j];
#pragma unroll
                for (int kj = 0; kj < 3; kj++) {
                    float4 w0 = *reinterpret_cast<const float4*>(&sw[ck][ki][kj][tc * 8]);
                    float4 w1 = *reinterpret_cast<const float4*>(&sw[ck][ki][kj][tc * 8 + 4]);
                    float wv[8] = {w0.x, w0.y, w0.z, w0.w, w1.x, w1.y, w1.z, w1.w};
#pragma unroll
                    for (int i = 0; i < 8; i++)
#pragma unroll
                        for (int j = 0; j < 8; j++)
                            acc[i][j] = fmaf(wv[i], win[j + kj], acc[i][j]);
                }
            }
        }
        __syncthreads();
    }

    // ---- fused epilogue: bias -> multiplier -> leaky relu -> tanh-GELU ----
    const int   oh = oh_base + trow;
    const float c0 = 0.7978845608028654f;  // sqrt(2/pi)
#pragma unroll
    for (int i = 0; i < 8; i++) {
        const int   co = co0 + tc * 8 + i;
        const float bi = bias[co];
        const float mu = mult[co];
#pragma unroll
        for (int j = 0; j < 8; j++) {
            const int ow = ow_base + tcg * 8 + j;
            float y = (acc[i][j] + bi) * mu;
            y = (y >= 0.f) ? y : 0.01f * y;
            float t = c0 * (y + 0.044715f * y * y * y);
            float g = 0.5f * y * (1.f + tanhf(t));
            if (oh < OHH && ow < OWW)
                out[(((size_t)b * COUTT + co) * OHH + oh) * OWW + ow] = g;
        }
    }
}

extern "C" void kernel_launch(void* const* d_in, const int* in_sizes, int n_in,
                              void* d_out, int out_size)
{
    const float* x    = (const float*)d_in[0];
    const float* w    = (const float*)d_in[1];
    const float* bias = (const float*)d_in[2];
    const float* mult = (const float*)d_in[3];
    float*       out  = (float*)d_out;

    dim3 grid((OWW + TILE_OW - 1) / TILE_OW,   // 4
              (OHH + TILE_OH - 1) / TILE_OH,   // 8
              BB * 4);                         // 32 batches x 4 cout chunks
    conv3x3_fused_kernel<<<grid, 256>>>(x, w, bias, mult, out);
}

// round 5
// speedup vs baseline: 1.0571x; 1.0011x over previous
#include <cuda_runtime.h>
#include <math.h>

// Problem constants
#define BB    32
#define CIN   64
#define HIN   128
#define WINP  128
#define COUTT 128
#define OHH   126
#define OWW   126

// Tiling
#define TILE_OH 16
#define TILE_OW 32
#define TILE_CO 32
#define CK      8     // cin chunk

// Block: 256 threads.
//   tc   = tid>>6  in [0,4)   -> cout sub-tile of 8 (co0 + tc*8 + 0..7)
//   tp   = tid&63
//   trow = tp>>2   in [0,16)  -> output row within tile
//   tcg  = tp&3    in [0,4)   -> 8-wide column group
// Each thread: acc[8 couts][8 cols] register tile (64 FMAs per weight-octet).

__global__ __launch_bounds__(256, 2)
void conv3x3_fused_kernel(const float* __restrict__ x,
                          const float* __restrict__ w,
                          const float* __restrict__ bias,
                          const float* __restrict__ mult,
                          float* __restrict__ out)
{
    // stride 35 (odd) -> verified conflict-free for the (row, colgroup) access set
    __shared__ float sx[CK][TILE_OH + 2][TILE_OW + 3];
    __shared__ float sw[CK][3][3][TILE_CO];

    const int tid  = threadIdx.x;
    const int tc   = tid >> 6;
    const int tp   = tid & 63;
    const int trow = tp >> 2;
    const int tcg  = tp & 3;

    const int ow_base = blockIdx.x * TILE_OW;
    const int oh_base = blockIdx.y * TILE_OH;
    const int b       = blockIdx.z >> 2;
    const int co0     = (blockIdx.z & 3) * TILE_CO;

    float acc[8][8];
#pragma unroll
    for (int i = 0; i < 8; i++)
#pragma unroll
        for (int j = 0; j < 8; j++) acc[i][j] = 0.f;

    for (int ci0 = 0; ci0 < CIN; ci0 += CK) {
        // ---- load input tile (CK x 18 x 34), zero-padded at image edges ----
        for (int idx = tid; idx < CK * (TILE_OH + 2) * (TILE_OW + 2); idx += 256) {
            int c  = idx % (TILE_OW + 2);
            int t  = idx / (TILE_OW + 2);
            int r  = t % (TILE_OH + 2);
            int ck = t / (TILE_OH + 2);
            int gh = oh_base + r;
            int gw = ow_base + c;
            float v = 0.f;
            if (gh < HIN && gw < WINP)
                v = x[(((size_t)b * CIN + ci0 + ck) * HIN + gh) * WINP + gw];
            sx[ck][r][c] = v;
        }
        // ---- load weights (CK x 3 x 3 x 32 couts) ----
        for (int idx = tid; idx < CK * 9 * TILE_CO; idx += 256) {
            int co = idx & 31;
            int t  = idx >> 5;
            int kk = t % 9;
            int ck = t / 9;
            sw[ck][kk / 3][kk % 3][co] =
                w[((size_t)(co0 + co) * CIN + ci0 + ck) * 9 + kk];
        }
        __syncthreads();

#pragma unroll 2
        for (int ck = 0; ck < CK; ck++) {
#pragma unroll
            for (int ki = 0; ki < 3; ki++) {
                // 10-wide sliding window covers all three kj shifts
                float win[10];
#pragma unroll
                for (int j = 0; j < 10; j++)
                    win[j] = sx[ck][trow + ki][tcg * 8 + j];
#pragma unroll
                for (int kj = 0; kj < 3; kj++) {
                    float4 w0 = *reinterpret_cast<const float4*>(&sw[ck][ki][kj][tc * 8]);
                    float4 w1 = *reinterpret_cast<const float4*>(&sw[ck][ki][kj][tc * 8 + 4]);
                    float wv[8] = {w0.x, w0.y, w0.z, w0.w, w1.x, w1.y, w1.z, w1.w};
#pragma unroll
                    for (int i = 0; i < 8; i++)
#pragma unroll
                        for (int j = 0; j < 8; j++)
                            acc[i][j] = fmaf(wv[i], win[j + kj], acc[i][j]);
                }
            }
        }
        __syncthreads();
    }

    // ---- fused epilogue: bias -> multiplier -> leaky relu -> tanh-GELU ----
    const int   oh = oh_base + trow;
    const float c0 = 0.7978845608028654f;  // sqrt(2/pi)
#pragma unroll
    for (int i = 0; i < 8; i++) {
        const int   co = co0 + tc * 8 + i;
        const float bi = bias[co];
        const float mu = mult[co];
#pragma unroll
        for (int j = 0; j < 8; j++) {
            const int ow = ow_base + tcg * 8 + j;
            float y = (acc[i][j] + bi) * mu;
            y = (y >= 0.f) ? y : 0.01f * y;
            float t = c0 * (y + 0.044715f * y * y * y);
            float g = 0.5f * y * (1.f + tanhf(t));
            if (oh < OHH && ow < OWW)
                out[(((size_t)b * COUTT + co) * OHH + oh) * OWW + ow] = g;
        }
    }
}

extern "C" void kernel_launch(void* const* d_in, const int* in_sizes, int n_in,
                              void* d_out, int out_size)
{
    const float* x    = (const float*)d_in[0];
    const float* w    = (const float*)d_in[1];
    const float* bias = (const float*)d_in[2];
    const float* mult = (const float*)d_in[3];
    float*       out  = (float*)d_out;

    dim3 grid((OWW + TILE_OW - 1) / TILE_OW,   // 4
              (OHH + TILE_OH - 1) / TILE_OH,   // 8
              BB * 4);                         // 32 batches x 4 cout chunks
    conv3x3_fused_kernel<<<grid, 256>>>(x, w, bias, mult, out);
}